// round 15
// baseline (speedup 1.0000x reference)
#include <cuda_runtime.h>
#include <cstddef>
#include <cstdint>

#define N_NODES 100000
#define N_EDGES 1600000
#define IN_CH   128
#define HEADS   4
#define OUT_CH  32
#define F_TOT   128   // HEADS*OUT_CH
#define MAX_SLOTS 256

// Scratch (static __device__ allocation; runtime alloc forbidden)
__device__ float    g_proj[(size_t)N_NODES * F_TOT];   // 51.2 MB
__device__ float    g_norm[(size_t)N_NODES * HEADS];   // 1.6 MB
__device__ unsigned g_slot[HEADS * MAX_SLOTS];         // hashed per-head max slots
__device__ float    g_hmax[HEADS];                     // final per-head max

// monotone float->uint map (order-preserving); inverse for readback
__device__ __forceinline__ unsigned fmap(float f) {
    unsigned u = __float_as_uint(f);
    return (u & 0x80000000u) ? ~u : (u | 0x80000000u);
}
__device__ __forceinline__ float funmap(unsigned u) {
    return __uint_as_float((u & 0x80000000u) ? (u & 0x7FFFFFFFu) : ~u);
}

// fast tanh: 2 MUFU + few FMA; rel err ~1e-6 (validated: pipeline rel_err 3.7e-7)
__device__ __forceinline__ float fast_tanh(float x) {
    float ax = fabsf(x);
    float e  = __expf(2.0f * ax);             // inf for large ax -> r = 1
    float r  = 1.0f - __fdividef(2.0f, e + 1.0f);
    return copysignf(r, x);
}

// packed f32x2 helpers (sm_100+; .rn rounding identical to scalar FFMA)
#define PACK2(dst, lo, hi) \
    asm("mov.b64 %0, {%1, %2};" : "=l"(dst) : "f"(lo), "f"(hi))
#define BCAST2(dst, v) \
    asm("mov.b64 %0, {%1, %1};" : "=l"(dst) : "f"(v))
#define FMA2(acc, a, b) \
    asm("fma.rn.f32x2 %0, %1, %2, %0;" : "+l"(acc) : "l"(a), "l"(b))
#define UNPACK2(lo, hi, src) \
    asm("mov.b64 {%0, %1}, %2;" : "=f"(lo), "=f"(hi) : "l"(src))

// cp.async 16B: global -> shared without registers
#define CP_ASYNC16(smem_u32, gptr) \
    asm volatile("cp.async.cg.shared.global [%0], [%1], 16;" \
                 :: "r"(smem_u32), "l"(gptr) : "memory")
#define CP_COMMIT()  asm volatile("cp.async.commit_group;" ::: "memory")
#define CP_WAIT(n)   asm volatile("cp.async.wait_group %0;" :: "n"(n) : "memory")

// ---------------------------------------------------------------------------
// GEMM v5: 128x128 tile / 256 threads, 8x8 microtile (FMA2), cp.async
// DOUBLE-BUFFERED k-pipeline: tile s+1's global->smem copies run during
// tile s's 1024 FMA2s, zero register cost. A row-major in smem (pad 20
// floats = 80B rows, 16B-aligned cp.async dst); a-frag = 8 broadcast LDS.32.
// ---------------------------------------------------------------------------
__global__ __launch_bounds__(256) void gemm_kernel(const float* __restrict__ x,
                                                   const float* __restrict__ Wm) {
    __shared__ float xs[2][128][20];   // [buf][row][k], pad 20 (80B rows)
    __shared__ float ws[2][16][128];   // [buf][k][col]
    const int t  = threadIdx.x;
    const int tx = t & 15;             // col group
    const int ty = t >> 4;             // row group
    const int rowBase = blockIdx.x * 128;

    unsigned long long acc2[8][4];     // 8 rows x 4 col-pairs (f32x2)
#pragma unroll
    for (int i = 0; i < 8; i++)
#pragma unroll
        for (int j = 0; j < 4; j++) acc2[i][j] = 0ull;

    // loader mappings (2 cp.async each for A and B per tile)
    // A: idx = t*2+rep in 0..511 -> row = idx>>2, c4 = (idx&3)*4
    // B: idx -> k = idx>>5, c4 = (idx&31)*4
    int aRow[2], aCol[2], bK[2], bC[2];
    const float* aSrc[2];
#pragma unroll
    for (int rep = 0; rep < 2; rep++) {
        int idx = t * 2 + rep;
        aRow[rep] = idx >> 2;
        aCol[rep] = (idx & 3) * 4;
        int gr = rowBase + aRow[rep];
        if (gr >= N_NODES) gr = N_NODES - 1;       // clamp (dup loads OK)
        aSrc[rep] = x + (size_t)gr * IN_CH + aCol[rep];
        bK[rep] = idx >> 5;
        bC[rep] = (idx & 31) * 4;
    }

    auto issue_tile = [&](int buf, int kk) {
#pragma unroll
        for (int rep = 0; rep < 2; rep++) {
            unsigned dstA = (unsigned)__cvta_generic_to_shared(
                &xs[buf][aRow[rep]][aCol[rep]]);
            CP_ASYNC16(dstA, aSrc[rep] + kk);
            unsigned dstB = (unsigned)__cvta_generic_to_shared(
                &ws[buf][bK[rep]][bC[rep]]);
            CP_ASYNC16(dstB, Wm + (size_t)(kk + bK[rep]) * F_TOT + bC[rep]);
        }
        CP_COMMIT();
    };

    issue_tile(0, 0);

#pragma unroll
    for (int s = 0; s < IN_CH / 16; s++) {
        const int buf = s & 1;
        if (s < IN_CH / 16 - 1) {
            issue_tile(buf ^ 1, (s + 1) * 16);
            CP_WAIT(1);                 // tile s complete, s+1 may be in flight
        } else {
            CP_WAIT(0);
        }
        __syncthreads();

#pragma unroll
        for (int k = 0; k < 16; k++) {
            float4 b0 = *(float4*)&ws[buf][k][tx * 8];
            float4 b1 = *(float4*)&ws[buf][k][tx * 8 + 4];
            unsigned long long bp[4];
            PACK2(bp[0], b0.x, b0.y);
            PACK2(bp[1], b0.z, b0.w);
            PACK2(bp[2], b1.x, b1.y);
            PACK2(bp[3], b1.z, b1.w);
#pragma unroll
            for (int i = 0; i < 8; i++) {
                unsigned long long ab;
                BCAST2(ab, xs[buf][ty * 8 + i][k]);
#pragma unroll
                for (int j = 0; j < 4; j++)
                    FMA2(acc2[i][j], ab, bp[j]);
            }
        }
        __syncthreads();                // all warps done with buf before reuse
    }

#pragma unroll
    for (int i = 0; i < 8; i++) {
        int r = rowBase + ty * 8 + i;
        if (r < N_NODES) {
            float4 o0, o1;
            UNPACK2(o0.x, o0.y, acc2[i][0]);
            UNPACK2(o0.z, o0.w, acc2[i][1]);
            UNPACK2(o1.x, o1.y, acc2[i][2]);
            UNPACK2(o1.z, o1.w, acc2[i][3]);
            *(float4*)(g_proj + (size_t)r * F_TOT + tx * 8)     = o0;
            *(float4*)(g_proj + (size_t)r * F_TOT + tx * 8 + 4) = o1;
        }
    }
}

// ---------------------------------------------------------------------------
// Edge kernel (R11 known-good, verbatim): one warp per edge, 8 edges/block,
// E/8 = 200000 blocks exactly. Lane L owns channels [4L,4L+4), head = L>>3.
// ---------------------------------------------------------------------------
__global__ __launch_bounds__(256) void edge_kernel(const int* __restrict__ ei,
                                                   const float* __restrict__ att,
                                                   float* __restrict__ out) {
    const int warpInBlk = threadIdx.x >> 5;
    const int lane      = threadIdx.x & 31;
    const int edge      = blockIdx.x * 8 + warpInBlk;

    __shared__ float smax[8][HEADS];

    const int row = __ldg(ei + edge);
    const int col = __ldg(ei + N_EDGES + edge);

    const float4 s4 = *(const float4*)(g_proj + (size_t)row * F_TOT + lane * 4);
    const float4 d4 = *(const float4*)(g_proj + (size_t)col * F_TOT + lane * 4);
    const float4 a4 = *(const float4*)(att + lane * 4);

    float p = fast_tanh(s4.x + d4.x) * a4.x
            + fast_tanh(s4.y + d4.y) * a4.y
            + fast_tanh(s4.z + d4.z) * a4.z
            + fast_tanh(s4.w + d4.w) * a4.w;

    // reduce within each 8-lane head group (all lanes get the sum)
    p += __shfl_xor_sync(0xffffffffu, p, 4);
    p += __shfl_xor_sync(0xffffffffu, p, 2);
    p += __shfl_xor_sync(0xffffffffu, p, 1);

    if ((lane & 7) == 0) smax[warpInBlk][lane >> 3] = p;

    const float w = __expf(p);

    float* op = out + (size_t)col * F_TOT + lane * 4;
    asm volatile("red.global.add.v4.f32 [%0], {%1,%2,%3,%4};"
                 :: "l"(op), "f"(s4.x * w), "f"(s4.y * w),
                    "f"(s4.z * w), "f"(s4.w * w)
                 : "memory");

    if ((lane & 7) == 0)
        atomicAdd(g_norm + (size_t)col * HEADS + (lane >> 3), w);

    __syncthreads();
    if (threadIdx.x < HEADS) {
        float m = smax[0][threadIdx.x];
#pragma unroll
        for (int wb = 1; wb < 8; wb++) m = fmaxf(m, smax[wb][threadIdx.x]);
        atomicMax(&g_slot[threadIdx.x * MAX_SLOTS + (blockIdx.x & (MAX_SLOTS - 1))],
                  fmap(m));
    }
}

// ---------------------------------------------------------------------------
// Reduce hashed max slots -> g_hmax[h]
// ---------------------------------------------------------------------------
__global__ __launch_bounds__(256) void maxreduce_kernel() {
    __shared__ unsigned sm[256];
    const int t = threadIdx.x;
    for (int h = 0; h < HEADS; h++) {
        sm[t] = g_slot[h * MAX_SLOTS + t];
        __syncthreads();
        for (int s = 128; s > 0; s >>= 1) {
            if (t < s) sm[t] = max(sm[t], sm[t + s]);
            __syncthreads();
        }
        if (t == 0) g_hmax[h] = funmap(sm[0]);
        __syncthreads();
    }
}

// ---------------------------------------------------------------------------
// Finalize: exact reference semantics including the 1e-12 clamp:
//   scale = exp(-max_h); out = out_acc*scale / max(norm_acc*scale, 1e-12)
// ---------------------------------------------------------------------------
__global__ __launch_bounds__(256) void finalize_kernel(float* __restrict__ out) {
    size_t i4 = (size_t)blockIdx.x * blockDim.x + threadIdx.x;
    if (i4 >= (size_t)N_NODES * (F_TOT / 4)) return;
    int n = (int)(i4 >> 5);
    int q = (int)(i4 & 31);
    int h = q >> 3;
    float scale = __expf(-g_hmax[h]);
    float nr    = g_norm[(size_t)n * HEADS + h] * scale;
    float inv   = scale / fmaxf(nr, 1e-12f);
    float4 v = *(float4*)(out + i4 * 4);
    v.x *= inv; v.y *= inv; v.z *= inv; v.w *= inv;
    *(float4*)(out + i4 * 4) = v;
}

// ---------------------------------------------------------------------------
extern "C" void kernel_launch(void* const* d_in, const int* in_sizes, int n_in,
                              void* d_out, int out_size) {
    const float* x   = (const float*)d_in[0];
    const int*   ei  = (const int*)d_in[1];    // int32 edge_index [2, E]
    const float* Wm  = (const float*)d_in[2];
    const float* att = (const float*)d_in[3];
    float*       out = (float*)d_out;

    void* normPtr = nullptr;
    void* slotPtr = nullptr;
    cudaGetSymbolAddress(&normPtr, g_norm);
    cudaGetSymbolAddress(&slotPtr, g_slot);

    cudaMemsetAsync(out, 0, (size_t)N_NODES * F_TOT * sizeof(float));
    cudaMemsetAsync(normPtr, 0, (size_t)N_NODES * HEADS * sizeof(float));
    cudaMemsetAsync(slotPtr, 0, HEADS * MAX_SLOTS * sizeof(unsigned));

    gemm_kernel<<<(N_NODES + 127) / 128, 256>>>(x, Wm);

    edge_kernel<<<N_EDGES / 8, 256>>>(ei, att, out);   // 200000 blocks exactly

    maxreduce_kernel<<<1, 256>>>();

    const long long finElems = (long long)N_NODES * (F_TOT / 4);
    finalize_kernel<<<(unsigned)((finElems + 255) / 256), 256>>>(out);
}